// round 14
// baseline (speedup 1.0000x reference)
#include <cuda_runtime.h>
#include <cuda_fp16.h>
#include <cstdint>

#define DIMK   4096
#define NEXP   64
#define BTOK   16384
#define MTILE  128
#define KB     64
#define NCHUNK (DIMK / KB)
#define NTHR   512
#define ABUF_SZ 16384               // per A buffer: fp16 128x64
#define BSTG_OFF 32768              // 4 stages x 8KB
#define BIAS_OFF 65536
#define CNT_OFF  65792
#define LIST_OFF 65808              // 64 ints
#define P_OFF    66064              // [8][64] floats
#define LR_OFF   68112              // 64 floats
#define SMEM_BYTES 68608
#define DELTA  2.5e-3f

// pre-swizzled fp16(w) tiles: [chunk][64e*64k fp16]
static __device__ __align__(16) unsigned short g_ws[NCHUNK][4096];

__device__ __forceinline__ unsigned smem_u32(const void* p) {
    return (unsigned)__cvta_generic_to_shared(p);
}
__device__ __forceinline__ void cpa16(unsigned dst, const void* src) {
    asm volatile("cp.async.cg.shared.global [%0], [%1], 16;" :: "r"(dst), "l"(src));
}
__device__ __forceinline__ void ldsm4(unsigned* r, unsigned a) {
    asm volatile("ldmatrix.sync.aligned.m8n8.x4.shared.b16 {%0,%1,%2,%3}, [%4];"
                 : "=r"(r[0]), "=r"(r[1]), "=r"(r[2]), "=r"(r[3]) : "r"(a));
}
#define MMA(d, a, b0v, b1v)                                                    \
    asm volatile(                                                              \
        "mma.sync.aligned.m16n8k16.row.col.f32.f16.f16.f32 "                   \
        "{%0,%1,%2,%3},{%4,%5,%6,%7},{%8,%9},{%0,%1,%2,%3};"                   \
        : "+f"((d)[0]), "+f"((d)[1]), "+f"((d)[2]), "+f"((d)[3])               \
        : "r"((a)[0]), "r"((a)[1]), "r"((a)[2]), "r"((a)[3]),                  \
          "r"(b0v), "r"(b1v))

__global__ void wsplit_kernel(const float* __restrict__ w) {
    const int idx = blockIdx.x * 256 + threadIdx.x;
    const int e = idx >> 12, k = idx & 4095;
    const unsigned short b0 = __half_as_ushort(__float2half_rn(w[idx]));
    const int c = k >> 6, kk = k & 63;
    const unsigned off = ((unsigned)e << 7) + (((unsigned)kk * 2) ^ ((e & 7) << 4));
    g_ws[c][off >> 1] = b0;
}

__global__ void __launch_bounds__(NTHR, 1)
mome_gate_mma(const float* __restrict__ h,
              const float* __restrict__ w,
              const float* __restrict__ bias,
              float* __restrict__ out)
{
    extern __shared__ char smc[];
    const unsigned smb = smem_u32(smc);
    const int tid  = threadIdx.x;
    const int lane = tid & 31;
    const int wid  = tid >> 5;       // 0..15
    const int wr   = wid >> 1;       // rows wr*16..+15
    const int we   = wid & 1;        // experts we*32..+31
    const size_t rowBase = (size_t)blockIdx.x * MTILE;

    if (tid == 0) *(int*)(smc + CNT_OFF) = 0;
    if (tid < NEXP) ((float*)(smc + BIAS_OFF))[tid] = bias[tid];

    // producer mapping: 512 thr cover 128 rows x 64 k; 4 rows/thread (stride 32)
    const int  prow = tid >> 4;      // 0..31
    const int  pu16 = tid & 15;      // float4 slot (kk = pu16*4)
    const float* hsrc0 = h + (rowBase + prow) * DIMK + pu16 * 4;

    // fragment geometry (PROVEN across R4..R13)
    const int mrow  = (lane & 7) + ((lane >> 3) & 1) * 8;
    const unsigned klane = ((unsigned)(lane >> 4)) * 16;
    const unsigned xorv  = ((unsigned)(lane & 7)) << 4;
    const unsigned aoff    = (unsigned)(wr * 16 + mrow) * 128;
    const unsigned browoff = (unsigned)(we * 32 + mrow) * 128;

    float acc[4][4];
#pragma unroll
    for (int n = 0; n < 4; n++)
#pragma unroll
        for (int q = 0; q < 4; q++) acc[n][q] = 0.f;

    float4 r[4];
    auto ldgA = [&](int c) {
#pragma unroll
        for (int i = 0; i < 4; i++)
            r[i] = *(const float4*)(hsrc0 + (size_t)i * 32 * DIMK + c * KB);
    };
    auto stsA = [&](int buf) {
        char* A0 = smc + buf * ABUF_SZ;
#pragma unroll
        for (int i = 0; i < 4; i++) {
            const int row = prow + i * 32;
            const unsigned boff = (unsigned)row * 128
                                + (((unsigned)pu16 * 8) ^ (((unsigned)row & 7) << 4));
            const float4 v = r[i];
            const __half2 p0 = __float22half2_rn(make_float2(v.x, v.y));
            const __half2 p1 = __float22half2_rn(make_float2(v.z, v.w));
            *(uint2*)(A0 + boff) =
                make_uint2(*reinterpret_cast<const unsigned*>(&p0),
                           *reinterpret_cast<const unsigned*>(&p1));
        }
    };
    auto cpB = [&](int c) {
        const unsigned sb = smb + BSTG_OFF + (c & 3) * 8192;
        cpa16(sb + tid * 16, (const char*)g_ws[c] + tid * 16);
        asm volatile("cp.async.commit_group;" ::: "memory");
    };

    auto compute = [&](int c) {
        const unsigned Ab0 = smb + (c & 1) * ABUF_SZ + aoff;
        const unsigned Bb0 = smb + BSTG_OFF + (c & 3) * 8192 + browoff;
#pragma unroll
        for (int kb = 0; kb < 4; kb++) {
            const unsigned ko = ((unsigned)kb * 32 + klane) ^ xorv;
            unsigned a0f[4], b00[4], b01[4];
            ldsm4(a0f, Ab0 + ko);
            ldsm4(b00, Bb0 + ko);
            ldsm4(b01, Bb0 + 2048 + ko);

            MMA(acc[0], a0f, b00[0], b00[2]);
            MMA(acc[1], a0f, b00[1], b00[3]);
            MMA(acc[2], a0f, b01[0], b01[2]);
            MMA(acc[3], a0f, b01[1], b01[3]);
        }
    };

    // prologue: A chunk0 staged, A chunk1 in regs, B 0..2 in flight
    ldgA(0);
    stsA(0);
    ldgA(1);
    cpB(0); cpB(1); cpB(2);

    for (int c = 0; c < NCHUNK; c++) {
        asm volatile("cp.async.wait_group 2;" ::: "memory");
        __syncthreads();                 // A[c&1] + B[c] visible
        if (c + 1 < NCHUNK) stsA((c + 1) & 1);
        if (c + 2 < NCHUNK) ldgA(c + 2);
        if (c + 3 < NCHUNK) cpB(c + 3);
        compute(c);
    }
    asm volatile("cp.async.wait_group 0;" ::: "memory");
    __syncthreads();

    // ---- logits -> smem: Ls[128][68] (champion-verbatim) ----
    float* Ls = (float*)smc;
    {
        const int rin = lane >> 2;
        const int cin = (lane & 3) * 2;
        const int r0i = wr * 16 + rin;
#pragma unroll
        for (int n = 0; n < 4; n++) {
            const int col = we * 32 + n * 8 + cin;
            Ls[r0i * 68 + col]           = acc[n][0];
            Ls[r0i * 68 + col + 1]       = acc[n][1];
            Ls[(r0i + 8) * 68 + col]     = acc[n][2];
            Ls[(r0i + 8) * 68 + col + 1] = acc[n][3];
        }
    }
    __syncthreads();

    // ---- per-row top-3 scan, flag near-ties ----
    const float* bias_s = (const float*)(smc + BIAS_OFF);
    if (tid < MTILE) {
        const float* lrow = &Ls[tid * 68];
        float v0 = -1e30f, v1 = -1e30f, v2 = -1e30f;
        int i0 = 0, i1 = 0;
#pragma unroll 8
        for (int e = 0; e < NEXP; e++) {
            const float v = lrow[e] + bias_s[e];
            if (v > v0)      { v2 = v1; v1 = v0; i1 = i0; v0 = v; i0 = e; }
            else if (v > v1) { v2 = v1; v1 = v; i1 = e; }
            else if (v > v2) { v2 = v; }
        }
        if ((v0 - v1 < DELTA) || (v1 - v2 < DELTA)) {
            const int slot = atomicAdd((int*)(smc + CNT_OFF), 1);
            if (slot < 64) ((int*)(smc + LIST_OFF))[slot] = tid;
        } else {
            const float t  = __expf(v1 - v0);
            const float w0 = 1.0f / (1.0f + t);
            const size_t g = rowBase + tid;
            out[2 * g]     = w0;
            out[2 * g + 1] = 1.0f - w0;
            float* oi = out + 2 * (size_t)BTOK;
            oi[2 * g]     = (float)i0;
            oi[2 * g + 1] = (float)i1;
        }
    }
    __syncthreads();

    // ---- exact fp32 rescue (champion-verbatim, 512 thr) ----
    int nf = *(const int*)(smc + CNT_OFF);
    if (nf > 64) nf = 64;
    float* P  = (float*)(smc + P_OFF);     // [8][64]
    float* Lr = (float*)(smc + LR_OFF);    // [64]
    for (int f = 0; f < nf; f++) {
        const int rrow = ((const int*)(smc + LIST_OFF))[f];
        const float* hr = h + (rowBase + rrow) * DIMK;
        const int e = tid & 63, q = tid >> 6;   // q 0..7
        const float* wp = w + (size_t)e * DIMK + q * 512;
        const float* hp = hr + q * 512;
        float s = 0.f;
        for (int k = 0; k < 512; k += 4) {
            const float4 hv = *(const float4*)(hp + k);
            const float4 wv = *(const float4*)(wp + k);
            s += hv.x * wv.x + hv.y * wv.y + hv.z * wv.z + hv.w * wv.w;
        }
        P[q * 64 + e] = s;
        __syncthreads();
        if (tid < NEXP) {
            float acc2 = bias_s[tid];
#pragma unroll
            for (int q2 = 0; q2 < 8; q2++) acc2 += P[q2 * 64 + tid];
            Lr[tid] = acc2;
        }
        __syncthreads();
        if (tid == 0) {
            float v0 = -1e30f, v1 = -1e30f;
            int i0 = 0, i1 = 0;
            for (int e2 = 0; e2 < NEXP; e2++) {
                const float v = Lr[e2];
                if (v > v0)      { v1 = v0; i1 = i0; v0 = v; i0 = e2; }
                else if (v > v1) { v1 = v; i1 = e2; }
            }
            const float t  = __expf(v1 - v0);
            const float w0 = 1.0f / (1.0f + t);
            const size_t g = rowBase + rrow;
            out[2 * g]     = w0;
            out[2 * g + 1] = 1.0f - w0;
            float* oi = out + 2 * (size_t)BTOK;
            oi[2 * g]     = (float)i0;
            oi[2 * g + 1] = (float)i1;
        }
        __syncthreads();
    }
}

extern "C" void kernel_launch(void* const* d_in, const int* in_sizes, int n_in,
                              void* d_out, int out_size)
{
    const float* h    = (const float*)d_in[0];
    const float* w    = (const float*)d_in[1];
    const float* bias = (const float*)d_in[2];
    float* out        = (float*)d_out;

    wsplit_kernel<<<(NEXP * DIMK) / 256, 256>>>(w);

    cudaFuncSetAttribute(mome_gate_mma,
                         cudaFuncAttributeMaxDynamicSharedMemorySize, SMEM_BYTES);
    mome_gate_mma<<<BTOK / MTILE, NTHR, SMEM_BYTES>>>(h, w, bias, out);
}

// round 15
// speedup vs baseline: 1.7029x; 1.7029x over previous
#include <cuda_runtime.h>
#include <cstdint>

#define DIMK   4096
#define NEXP   64
#define BTOK   16384
#define MTILE  128
#define KB     64
#define NCH    (DIMK / KB)
#define NTHR   256
#define NSTG   3
#define STG    49152                 // 32KB Hs(fp32 128x64) + 16KB Ws(fp32 64x64)
#define BIAS_OFF 147456
#define SMEM_BYTES 147712

__device__ __forceinline__ unsigned smem_u32(const void* p) {
    return (unsigned)__cvta_generic_to_shared(p);
}
__device__ __forceinline__ void cpa16(unsigned dst, const void* src) {
    asm volatile("cp.async.cg.shared.global [%0], [%1], 16;" :: "r"(dst), "l"(src));
}
__device__ __forceinline__ void ffma2(unsigned long long& d,
                                      unsigned long long a,
                                      unsigned long long b) {
    asm("fma.rn.f32x2 %0, %1, %2, %0;" : "+l"(d) : "l"(a), "l"(b));
}

__global__ void __launch_bounds__(NTHR, 1)
mome_gate_f2(const float* __restrict__ h,
             const float* __restrict__ w,
             const float* __restrict__ bias,
             float* __restrict__ out)
{
    extern __shared__ char smc[];
    const unsigned smb = smem_u32(smc);
    const int tid = threadIdx.x;
    const int kg  = tid >> 7;        // k-group: 0 -> k 0..31, 1 -> k 32..63 of chunk
    const int t   = tid & 127;
    const int er  = t & 7;           // experts er, er+8, ..., er+56
    const int rr  = t >> 3;          // rows    rr, rr+16, ..., rr+112
    const size_t rowBase = (size_t)blockIdx.x * MTILE;

    if (tid < NEXP) ((float*)(smc + BIAS_OFF))[tid] = bias[tid];

    // XOR swizzle constants (8B units): unit_phys = unit ^ ((row&7)<<2)
    const unsigned hx = ((unsigned)(rr & 7)) << 2;
    const unsigned wx = ((unsigned)er) << 2;

    unsigned long long acc[8][8];
#pragma unroll
    for (int i = 0; i < 8; i++)
#pragma unroll
        for (int j = 0; j < 8; j++) acc[i][j] = 0ull;

    auto loadAB = [&](int c, int s) {
        const unsigned sb = smb + s * STG;
        // Hs: 128 rows x 16 x 16B ; 8 cpa16/thread
#pragma unroll
        for (int j = 0; j < 8; j++) {
            const int idx = tid + j * 256;
            const int row = idx >> 4;
            const int u4  = idx & 15;
            const unsigned du = ((unsigned)(2 * u4)) ^ (((unsigned)(row & 7)) << 2);
            cpa16(sb + (unsigned)row * 256 + (du << 3),
                  h + (rowBase + row) * DIMK + c * KB + u4 * 4);
        }
        // Ws: 64 rows x 16 x 16B ; 4 cpa16/thread
#pragma unroll
        for (int j = 0; j < 4; j++) {
            const int idx = tid + j * 256;
            const int e  = idx >> 4;
            const int u4 = idx & 15;
            const unsigned du = ((unsigned)(2 * u4)) ^ (((unsigned)(e & 7)) << 2);
            cpa16(sb + 32768 + (unsigned)e * 256 + (du << 3),
                  w + (size_t)e * DIMK + c * KB + u4 * 4);
        }
        asm volatile("cp.async.commit_group;" ::: "memory");
    };

    auto compute = [&](int s) {
        const char* Hb = smc + s * STG;
        const char* Wb = Hb + 32768;
#pragma unroll
        for (int k4 = 0; k4 < 8; k4++) {
            const unsigned p = (unsigned)((kg * 8 + k4) * 2);   // 8B-unit index (even)
            ulonglong2 hv[8], wv[8];
#pragma unroll
            for (int i = 0; i < 8; i++) {
                const int row = rr + 16 * i;
                hv[i] = *(const ulonglong2*)(Hb + row * 256 + ((p ^ hx) << 3));
            }
#pragma unroll
            for (int j = 0; j < 8; j++) {
                const int e = er + 8 * j;
                wv[j] = *(const ulonglong2*)(Wb + e * 256 + ((p ^ wx) << 3));
            }
#pragma unroll
            for (int i = 0; i < 8; i++)
#pragma unroll
                for (int j = 0; j < 8; j++) {
                    ffma2(acc[i][j], hv[i].x, wv[j].x);
                    ffma2(acc[i][j], hv[i].y, wv[j].y);
                }
        }
    };

    // proven 3-stage pipeline (R12 shape): load c+2, wait<=1, one sync per chunk
    loadAB(0, 0);
    loadAB(1, 1);

    int s = 0;
    for (int c = 0; c < NCH; c++) {
        asm volatile("cp.async.wait_group 1;" ::: "memory");
        __syncthreads();
        if (c + 2 < NCH) {
            int ns = s + 2; if (ns >= NSTG) ns -= NSTG;
            loadAB(c + 2, ns);
        }
        compute(s);
        if (++s == NSTG) s = 0;
    }
    asm volatile("cp.async.wait_group 0;" ::: "memory");
    __syncthreads();

    // ---- epilogue: Ls[2][128][66], combine k-halves later ----
    float* Ls = (float*)smc;
    {
        float* Lg = Ls + kg * 8448;
#pragma unroll
        for (int i = 0; i < 8; i++) {
            const int row = rr + 16 * i;
#pragma unroll
            for (int j = 0; j < 8; j++) {
                const int e = er + 8 * j;
                const unsigned long long a = acc[i][j];
                const float lo = __uint_as_float((unsigned)(a & 0xffffffffull));
                const float hi = __uint_as_float((unsigned)(a >> 32));
                Lg[row * 66 + e] = lo + hi;
            }
        }
    }
    __syncthreads();

    // ---- per-row top-2 (exact fp32 logits; no rescue needed) ----
    const float* bias_s = (const float*)(smc + BIAS_OFF);
    if (tid < MTILE) {
        const float* l0 = &Ls[tid * 66];
        const float* l1 = &Ls[8448 + tid * 66];
        float v0 = -1e30f, v1 = -1e30f;
        int i0 = 0, i1 = 0;
#pragma unroll 8
        for (int e = 0; e < NEXP; e++) {
            const float v = l0[e] + l1[e] + bias_s[e];
            if (v > v0)      { v1 = v0; i1 = i0; v0 = v; i0 = e; }
            else if (v > v1) { v1 = v; i1 = e; }
        }
        const float tt = __expf(v1 - v0);
        const float w0 = 1.0f / (1.0f + tt);
        const size_t g = rowBase + tid;
        out[2 * g]     = w0;
        out[2 * g + 1] = 1.0f - w0;
        float* oi = out + 2 * (size_t)BTOK;
        oi[2 * g]     = (float)i0;
        oi[2 * g + 1] = (float)i1;
    }
}

extern "C" void kernel_launch(void* const* d_in, const int* in_sizes, int n_in,
                              void* d_out, int out_size)
{
    const float* h    = (const float*)d_in[0];
    const float* w    = (const float*)d_in[1];
    const float* bias = (const float*)d_in[2];
    float* out        = (float*)d_out;

    cudaFuncSetAttribute(mome_gate_f2,
                         cudaFuncAttributeMaxDynamicSharedMemorySize, SMEM_BYTES);
    mome_gate_f2<<<BTOK / MTILE, NTHR, SMEM_BYTES>>>(h, w, bias, out);
}